// round 12
// baseline (speedup 1.0000x reference)
#include <cuda_runtime.h>
#include <cstdint>
#include <cstddef>
#include <math.h>

#define SEQ    2048
#define BATCH  64
#define HID    512
#define INDIM  256

typedef unsigned long long u64;

// ---------------- device globals (allocation-free scratch) ----------------
// flags[((half*8+bg)<<7) + tile], monotonic: value base+t+1 => h(t) published
__device__ __align__(16) unsigned g_flags0[2048];
__device__ __align__(16) unsigned g_flags1[2048];
// transposed hidden states: slot s holds h(s-1); slot 0 = initial h0
__device__ float g_h0T[(size_t)(SEQ + 1) * HID * BATCH];
__device__ float g_h1T[(size_t)(SEQ + 1) * HID * BATCH];
// transposed input: g_xT[t][k][b]
__device__ float g_xT[(size_t)SEQ * INDIM * BATCH];

// ---------------- packed fp32x2 + memory-model helpers ----------------
__device__ __forceinline__ u64 ffma2(u64 a, u64 b, u64 c) {
    u64 d;
    asm("fma.rn.f32x2 %0, %1, %2, %3;" : "=l"(d) : "l"(a), "l"(b), "l"(c));
    return d;
}
__device__ __forceinline__ u64 fadd2(u64 a, u64 b) {
    u64 d;
    asm("add.rn.f32x2 %0, %1, %2;" : "=l"(d) : "l"(a), "l"(b));
    return d;
}
__device__ __forceinline__ u64 splat2(float x) {
    u64 d;
    asm("mov.b64 %0, {%1, %1};" : "=l"(d) : "f"(x));
    return d;
}
__device__ __forceinline__ float f2lo(u64 v) { return __uint_as_float((unsigned)v); }
__device__ __forceinline__ float f2hi(u64 v) { return __uint_as_float((unsigned)(v >> 32)); }

__device__ __forceinline__ u64 shflx64(u64 v, int m) {
    unsigned lo = (unsigned)v, hi = (unsigned)(v >> 32);
    lo = __shfl_xor_sync(0xffffffffu, lo, m);
    hi = __shfl_xor_sync(0xffffffffu, hi, m);
    return ((u64)hi << 32) | (u64)lo;
}
__device__ __forceinline__ u64 shfli64(u64 v, int src) {
    unsigned lo = (unsigned)v, hi = (unsigned)(v >> 32);
    lo = __shfl_sync(0xffffffffu, lo, src);
    hi = __shfl_sync(0xffffffffu, hi, src);
    return ((u64)hi << 32) | (u64)lo;
}
__device__ __forceinline__ unsigned ld_rlx(const unsigned* p) {
    unsigned v;
    asm volatile("ld.relaxed.gpu.u32 %0, [%1];" : "=r"(v) : "l"(p));
    return v;
}
__device__ __forceinline__ uint4 ldv4_rlx(const unsigned* p) {
    uint4 v;
    asm volatile("ld.relaxed.gpu.v4.u32 {%0,%1,%2,%3}, [%4];"
                 : "=r"(v.x), "=r"(v.y), "=r"(v.z), "=r"(v.w) : "l"(p));
    return v;
}
__device__ __forceinline__ void st_rlx(unsigned* p, unsigned v) {
    asm volatile("st.relaxed.gpu.u32 [%0], %1;" :: "l"(p), "r"(v) : "memory");
}
__device__ __forceinline__ void fence_acq() {
    asm volatile("fence.acq_rel.gpu;" ::: "memory");
}
__device__ __forceinline__ float sigf(float x) { return 1.0f / (1.0f + __expf(-x)); }
__device__ __forceinline__ float tanhfast(float x) {
    return 2.0f / (1.0f + __expf(-2.0f * x)) - 1.0f;
}

// ---------------- transpose kernels (run once, before the recurrences) ----
__global__ void __launch_bounds__(256)
xpose_x(const float* __restrict__ x)   // x[t][b][k] -> g_xT[t][k][b]
{
    __shared__ float tl[32][65];
    const int t  = blockIdx.x >> 3;
    const int k0 = (blockIdx.x & 7) * 32;
#pragma unroll
    for (int it = 0; it < 8; it++) {
        int idx = threadIdx.x + 256 * it;
        int b = idx >> 5, kk = idx & 31;
        tl[kk][b] = x[((size_t)t * BATCH + b) * INDIM + k0 + kk];
    }
    __syncthreads();
#pragma unroll
    for (int it = 0; it < 8; it++) {
        int idx = threadIdx.x + 256 * it;
        int kk = idx >> 6, b = idx & 63;
        g_xT[((size_t)t * INDIM + k0 + kk) * 64 + b] = tl[kk][b];
    }
}

__global__ void __launch_bounds__(256)
xpose_h0(const float* __restrict__ h0) // h0[layer][b][hid] -> slot 0 of h_T
{
    __shared__ float tl[32][65];
    const int layer = blockIdx.x >> 4;
    const int k0    = (blockIdx.x & 15) * 32;
#pragma unroll
    for (int it = 0; it < 8; it++) {
        int idx = threadIdx.x + 256 * it;
        int b = idx >> 5, kk = idx & 31;
        tl[kk][b] = h0[((size_t)layer * BATCH + b) * HID + k0 + kk];
    }
    __syncthreads();
    float* dst = layer ? g_h1T : g_h0T;
#pragma unroll
    for (int it = 0; it < 8; it++) {
        int idx = threadIdx.x + 256 * it;
        int kk = idx >> 6, b = idx & 63;
        dst[(size_t)(k0 + kk) * 64 + b] = tl[kk][b];
    }
}

// ---------------- GEMM fragment: NJ j-steps, acts direct from gmem --------
// wb = w_sm + (rowBase + lane)*16 ; ab = act + lane*64 + boff
// sk = (lane>>1)&3 : quad rotation making the 4 LDS.128 conflict-free.
template<int NJ>
__device__ __forceinline__ void gpart(u64 (&acc)[8][4],
                                      const float* __restrict__ wb,
                                      const float* __restrict__ ab,
                                      int sk)
{
    float4 a = *(const float4*)ab;
#pragma unroll
    for (int j = 0; j < NJ; j++) {
        float4 an = make_float4(0.f, 0.f, 0.f, 0.f);
        if (j + 1 < NJ) an = *(const float4*)(ab + (size_t)(j + 1) * 2048);
        u64 w2[8];
#pragma unroll
        for (int i = 0; i < 4; i++) {
            int q = i ^ sk;
            ulonglong2 wq = *(const ulonglong2*)(wb + j * 512 + q * 4);
            w2[2 * q] = wq.x; w2[2 * q + 1] = wq.y;
        }
        u64 a2[4];
        a2[0] = splat2(a.x); a2[1] = splat2(a.y);
        a2[2] = splat2(a.z); a2[3] = splat2(a.w);
#pragma unroll
        for (int b = 0; b < 4; b++)
#pragma unroll
            for (int p = 0; p < 8; p++)
                acc[p][b] = ffma2(w2[p], a2[b], acc[p][b]);
        a = an;
    }
}

// =====================================================================
// Persistent LSTM layer, v8: free-running warps, transposed exchange.
//  256 CTAs (128 tiles x 2 halves) x 256 thr; 2 CTAs/SM.
//  CTA = 4 hu x 32 batches; warp bg owns 4 hu x 4 batches.
//  Thread: 8 gate-pairs x 4 batches (32 f32x2 accs), k-split 32.
//  Acts read directly from gmem L2 (transposed layout) - NO staging,
//  NO act SMEM, NO __syncthreads in the loop. Per-warp flags + poll.
// =====================================================================
template<int NJX>
__global__ void __launch_bounds__(256, 2)
lstm_t(const float* __restrict__ wHg,   // [4H][HID]   recurrent weights
       const float* __restrict__ wXg,   // [4H][KX]    input weights
       const float* __restrict__ bA, const float* __restrict__ bB,
       const float* __restrict__ c0l,   // [BATCH][HID] layer slice
       const float* __restrict__ actX0, // x operand, step t at +t*XS
       float* __restrict__ hT,          // own h_T slots (read t, write t+1)
       unsigned* __restrict__ flags)
{
    constexpr int    KX = NJX * 32;
    constexpr int    K  = HID + KX;
    constexpr size_t XS = (size_t)KX * 64;
    constexpr size_t HS = (size_t)HID * 64;

    extern __shared__ float smem[];
    float* w_sm    = smem;               // K*16, rows: [w_hh(512) | w_x(KX)]
    float* bias_sm = w_sm + K * 16;      // 16

    const int tid  = threadIdx.x;
    const int lane = tid & 31;
    const int bg   = tid >> 5;           // 0..7
    const int half = blockIdx.x & 1;
    const int tile = blockIdx.x >> 1;    // 0..127
    const int hu_base = tile * 4;
    const int boff    = half * 32 + bg * 4;
    const int fidx    = ((half * 8 + bg) << 7) + tile;

    // ---- one-time: weights into SMEM (16 floats/row: [gate][hp][sub]) ----
    for (int r = 0; r < 16; r++) {
        int gate = r >> 2, hl = r & 3;
        const float* wrH = wHg + (size_t)(gate * HID + hu_base + hl) * HID;
        const float* wrX = wXg + (size_t)(gate * HID + hu_base + hl) * KX;
        int col = gate * 4 + (hl >> 1) * 2 + (hl & 1);
        for (int k = tid; k < K; k += 256) {
            float v = (k < HID) ? wrH[k] : wrX[k - HID];
            w_sm[k * 16 + col] = v;
        }
    }
    if (tid < 16) {
        int gate = tid >> 2, hl = tid & 3;
        int R = gate * HID + hu_base + hl;
        bias_sm[gate * 4 + (hl >> 1) * 2 + (hl & 1)] = bA[R] + bB[R];
    }
    __syncthreads();                     // weights/bias ready (only CTA sync)

    const unsigned base = ld_rlx(&flags[fidx]);

    const int sk = (lane >> 1) & 3;      // constant: ((k>>1)&3) for k=lane+32j
    const int hp = (lane >> 2) & 1;      // owned hu-pair (lanes 0-7 canonical)
    const int bl = lane & 3;
    const int hu0  = hu_base + hp * 2;
    const int batc = boff + bl;

    u64 bias2[4];
#pragma unroll
    for (int g = 0; g < 4; g++) bias2[g] = ((const u64*)bias_sm)[g * 2 + hp];

    float c0r = c0l[(size_t)batc * HID + hu0];
    float c1r = c0l[(size_t)batc * HID + hu0 + 1];

    const float* wbH = w_sm + lane * 16;
    const float* wbX = w_sm + (size_t)(HID + lane) * 16;
    const unsigned* fpoll = flags + ((half * 8 + bg) << 7) + lane * 4;

    u64 acc[8][4];

#define ACCF(i) acc[(i) >> 2][(i) & 3]

    for (int t = 0; t < SEQ; ++t) {
#pragma unroll
        for (int p = 0; p < 8; p++)
#pragma unroll
            for (int b = 0; b < 4; b++) acc[p][b] = 0ull;

        // ---- x-part (no recurrence dependency; covers others' latency) ----
        gpart<NJX>(acc, wbX, actX0 + (size_t)t * XS + (size_t)lane * 64 + boff, sk);

        // ---- poll h(t-1): 4 flags per lane, one relaxed v4 load ----
        if (t > 0) {
            const unsigned target = base + (unsigned)t;
            for (;;) {
                uint4 f = ldv4_rlx(fpoll);
                bool ok = ((int)(f.x - target) >= 0) && ((int)(f.y - target) >= 0) &&
                          ((int)(f.z - target) >= 0) && ((int)(f.w - target) >= 0);
                if (__all_sync(0xffffffffu, ok)) break;
            }
            fence_acq();
        }

        // ---- h-part ----
        gpart<16>(acc, wbH, hT + (size_t)t * HS + (size_t)lane * 64 + boff, sk);

        // ---- intra-warp selection-compaction reduction (32 lanes) ----
#pragma unroll
        for (int i = 0; i < 16; i++) {
            u64 lo = ACCF(i), hi = ACCF(i + 16);
            u64 mine = (lane & 16) ? hi : lo;
            u64 give = (lane & 16) ? lo : hi;
            ACCF(i) = fadd2(mine, shflx64(give, 16));
        }
#pragma unroll
        for (int i = 0; i < 8; i++) {
            u64 lo = ACCF(i), hi = ACCF(i + 8);
            u64 mine = (lane & 8) ? hi : lo;
            u64 give = (lane & 8) ? lo : hi;
            ACCF(i) = fadd2(mine, shflx64(give, 8));
        }
#pragma unroll
        for (int i = 0; i < 4; i++) {
            u64 lo = ACCF(i), hi = ACCF(i + 4);
            u64 mine = (lane & 4) ? hi : lo;
            u64 give = (lane & 4) ? lo : hi;
            ACCF(i) = fadd2(mine, shflx64(give, 4));
        }
#pragma unroll
        for (int i = 0; i < 2; i++) {
            u64 lo = ACCF(i), hi = ACCF(i + 2);
            u64 mine = (lane & 2) ? hi : lo;
            u64 give = (lane & 2) ? lo : hi;
            ACCF(i) = fadd2(mine, shflx64(give, 2));
        }
        {
            u64 lo = ACCF(0), hi = ACCF(1);
            u64 mine = (lane & 1) ? hi : lo;
            u64 give = (lane & 1) ? lo : hi;
            ACCF(0) = fadd2(mine, shflx64(give, 1));
        }
        u64 fin = ACCF(0);   // lane l: pair p=l>>2, batch b=l&3

        // gather all 4 gates for (hp, bl): source flat = g*8 + (lane&7)
        u64 gv[4];
#pragma unroll
        for (int g = 0; g < 4; g++)
            gv[g] = fadd2(shfli64(fin, g * 8 + (lane & 7)), bias2[g]);

        float ig0 = sigf(f2lo(gv[0])), ig1 = sigf(f2hi(gv[0]));
        float fg0 = sigf(f2lo(gv[1])), fg1 = sigf(f2hi(gv[1]));
        float gg0 = tanhfast(f2lo(gv[2])), gg1 = tanhfast(f2hi(gv[2]));
        float og0 = sigf(f2lo(gv[3])), og1 = sigf(f2hi(gv[3]));
        c0r = fg0 * c0r + ig0 * gg0;
        c1r = fg1 * c1r + ig1 * gg1;
        float h0v = og0 * tanhfast(c0r);
        float h1v = og1 * tanhfast(c1r);

        // transposed store: h_T[t+1][hu][batch]
        if (lane < 8) {
            float* hdst = hT + (size_t)(t + 1) * HS;
            hdst[(size_t)hu0 * 64 + batc]       = h0v;
            hdst[(size_t)(hu0 + 1) * 64 + batc] = h1v;
        }

        // publish: per-warp, no CTA barrier
        __threadfence();
        __syncwarp();
        if (lane == 0) st_rlx(flags + fidx, base + (unsigned)(t + 1));
    }
#undef ACCF
}

// ---------------- output head: sigmoid(h1 . w_out + b_out) ----------------
__global__ void __launch_bounds__(256)
head_kernel(const float* __restrict__ w_out, const float* __restrict__ b_out,
            float* __restrict__ out)
{
    __shared__ float wsm[HID];
    __shared__ float ps[4][64];
    const int t = blockIdx.x;
    for (int i = threadIdx.x; i < HID; i += 256) wsm[i] = w_out[i];
    __syncthreads();
    const int b = threadIdx.x & 63, r = threadIdx.x >> 6;
    const float* h = g_h1T + (size_t)(t + 1) * HID * 64;
    float s = 0.f;
#pragma unroll 4
    for (int i = 0; i < 128; i++) {
        int hu = i * 4 + r;
        s += h[(size_t)hu * 64 + b] * wsm[hu];
    }
    ps[r][b] = s;
    __syncthreads();
    if (r == 0) {
        float tot = ps[0][b] + ps[1][b] + ps[2][b] + ps[3][b] + b_out[0];
        out[(size_t)t * 64 + b] = 1.f / (1.f + expf(-tot));
    }
}

extern "C" void kernel_launch(void* const* d_in, const int* in_sizes, int n_in,
                              void* d_out, int out_size)
{
    (void)in_sizes; (void)n_in; (void)out_size;
    const float* input = (const float*)d_in[0];
    const float* h0    = (const float*)d_in[1];
    const float* c0    = (const float*)d_in[2];
    const float* w_ih0 = (const float*)d_in[3];
    const float* w_hh0 = (const float*)d_in[4];
    const float* b_ih0 = (const float*)d_in[5];
    const float* b_hh0 = (const float*)d_in[6];
    const float* w_ih1 = (const float*)d_in[7];
    const float* w_hh1 = (const float*)d_in[8];
    const float* b_ih1 = (const float*)d_in[9];
    const float* b_hh1 = (const float*)d_in[10];
    const float* w_out = (const float*)d_in[11];
    const float* b_out = (const float*)d_in[12];
    float* out = (float*)d_out;

    float *h0Tp, *h1Tp, *xTp;
    unsigned *f0p, *f1p;
    cudaGetSymbolAddress((void**)&h0Tp, g_h0T);
    cudaGetSymbolAddress((void**)&h1Tp, g_h1T);
    cudaGetSymbolAddress((void**)&xTp,  g_xT);
    cudaGetSymbolAddress((void**)&f0p,  g_flags0);
    cudaGetSymbolAddress((void**)&f1p,  g_flags1);

    const int smem0 = (768  * 16 + 16) * (int)sizeof(float);  // 49,216
    const int smem1 = (1024 * 16 + 16) * (int)sizeof(float);  // 65,600
    cudaFuncSetAttribute(lstm_t<8>,  cudaFuncAttributeMaxDynamicSharedMemorySize, smem0);
    cudaFuncSetAttribute(lstm_t<16>, cudaFuncAttributeMaxDynamicSharedMemorySize, smem1);

    xpose_x<<<SEQ * 8, 256>>>(input);
    xpose_h0<<<32, 256>>>(h0);

    // layer 0: K = 512(h) + 256(x); acts x from g_xT, h from g_h0T slots
    lstm_t<8><<<256, 256, smem0>>>(w_hh0, w_ih0, b_ih0, b_hh0,
                                   c0, xTp, h0Tp, f0p);
    // layer 1: K = 512(h1) + 512(h0); x operand = h0(t) = g_h0T slot t+1
    lstm_t<16><<<256, 256, smem1>>>(w_hh1, w_ih1, b_ih1, b_hh1,
                                    c0 + (size_t)BATCH * HID,
                                    h0Tp + (size_t)HID * 64, h1Tp, f1p);

    head_kernel<<<SEQ, 256>>>(w_out, b_out, out);
}

// round 13
// speedup vs baseline: 11.5921x; 11.5921x over previous
#include <cuda_runtime.h>
#include <cstdint>
#include <cstddef>
#include <math.h>

#define SEQ    2048
#define BATCH  64
#define HID    512
#define NTHR   256

typedef unsigned long long u64;

// ---------------- device globals (allocation-free scratch) ----------------
// per-layer flags[half*128 + tile], monotonic: base+t+1 => h(t) published
__device__ __align__(16) unsigned g_flagsA[256];
__device__ __align__(16) unsigned g_flagsB[256];
__device__ float g_h0_all[(size_t)SEQ * BATCH * HID];
__device__ float g_h1_all[(size_t)SEQ * BATCH * HID];

// ---------------- packed fp32x2 + memory-model helpers ----------------
__device__ __forceinline__ u64 ffma2(u64 a, u64 b, u64 c) {
    u64 d;
    asm("fma.rn.f32x2 %0, %1, %2, %3;" : "=l"(d) : "l"(a), "l"(b), "l"(c));
    return d;
}
__device__ __forceinline__ u64 fadd2(u64 a, u64 b) {
    u64 d;
    asm("add.rn.f32x2 %0, %1, %2;" : "=l"(d) : "l"(a), "l"(b));
    return d;
}
__device__ __forceinline__ u64 splat2(float x) {
    u64 d;
    asm("mov.b64 %0, {%1, %1};" : "=l"(d) : "f"(x));
    return d;
}
__device__ __forceinline__ float f2lo(u64 v) { return __uint_as_float((unsigned)v); }
__device__ __forceinline__ float f2hi(u64 v) { return __uint_as_float((unsigned)(v >> 32)); }

__device__ __forceinline__ u64 shflx64(u64 v, int m) {
    unsigned lo = (unsigned)v, hi = (unsigned)(v >> 32);
    lo = __shfl_xor_sync(0xffffffffu, lo, m);
    hi = __shfl_xor_sync(0xffffffffu, hi, m);
    return ((u64)hi << 32) | (u64)lo;
}
__device__ __forceinline__ u64 shfli64(u64 v, int src) {
    unsigned lo = (unsigned)v, hi = (unsigned)(v >> 32);
    lo = __shfl_sync(0xffffffffu, lo, src);
    hi = __shfl_sync(0xffffffffu, hi, src);
    return ((u64)hi << 32) | (u64)lo;
}
__device__ __forceinline__ unsigned ld_rlx(const unsigned* p) {
    unsigned v;
    asm volatile("ld.relaxed.gpu.u32 %0, [%1];" : "=r"(v) : "l"(p));
    return v;
}
__device__ __forceinline__ uint4 ldv4_rlx(const unsigned* p) {
    uint4 v;
    asm volatile("ld.relaxed.gpu.v4.u32 {%0,%1,%2,%3}, [%4];"
                 : "=r"(v.x), "=r"(v.y), "=r"(v.z), "=r"(v.w) : "l"(p));
    return v;
}
__device__ __forceinline__ void st_rlx(unsigned* p, unsigned v) {
    asm volatile("st.relaxed.gpu.u32 [%0], %1;" :: "l"(p), "r"(v) : "memory");
}
__device__ __forceinline__ void fence_acq() {
    asm volatile("fence.acq_rel.gpu;" ::: "memory");
}
__device__ __forceinline__ float sigf(float x) { return 1.0f / (1.0f + __expf(-x)); }
__device__ __forceinline__ float tanhfast(float x) {
    return 2.0f / (1.0f + __expf(-2.0f * x)) - 1.0f;
}

// =====================================================================
// Persistent fused LSTM layer, v9: half-size CTAs, 2 co-resident/SM.
//  Grid 256 = 128 tiles x 2 halves; CTA = 4 hu (16 gate rows) x 32 b.
//  256 thr = 8 warps (rg = wrp&1: hu-pair; bg = wrp>>1: 8 batches).
//  Thread: 4 gate-pairs x 8 batches f32x2 accs (same as proven R7).
//  Weights: 16 floats/k, quad rotation (q ^ ((k>>1)&3)) -> LDS.128
//  conflict-free. Acts: 32 floats/k, quad ^ (k&7) (proven). SMEM
//  98,368 B -> 2 CTAs/SM: HW interleaves two independent pipelines.
// =====================================================================
template<int DIN>
__global__ void __launch_bounds__(NTHR, 2)
lstm_layer(const float* __restrict__ x,       // [SEQ][BATCH][DIN] (or h0_all)
           const float* __restrict__ h0l,     // [BATCH][HID]
           const float* __restrict__ c0l,     // [BATCH][HID]
           const float* __restrict__ w_ih,    // [4H][DIN]
           const float* __restrict__ w_hh,    // [4H][HID]
           const float* __restrict__ b_ih,    // [4H]
           const float* __restrict__ b_hh,    // [4H]
           float* __restrict__ h_all,         // [SEQ][BATCH][HID]
           unsigned* __restrict__ flags)      // [256]
{
    constexpr int K    = HID + DIN;           // 768 or 1024
    constexpr int NBUF = (DIN == 256) ? 3 : 2;

    extern __shared__ float smem[];
    float* w_sm    = smem;                    // K*16
    float* buf0    = w_sm + K * 16;           // 128*32
    float* buf1    = buf0 + 128 * 32;         // 128*32
    float* buf2    = (NBUF == 3) ? buf1 + 128 * 32 : buf1;  // L0 only
    float* bias_sm = buf1 + (NBUF - 1) * 128 * 32;          // 16

    const int tid  = threadIdx.x;
    const int lane = tid & 31;
    const int wrp  = tid >> 5;                // 0..7
    const int rg   = wrp & 1;                 // hu-pair group
    const int bg   = wrp >> 1;                // batch group (8 batches)
    const int half = blockIdx.x & 1;
    const int tile = blockIdx.x >> 1;         // 0..127
    const int hu_base = tile * 4;
    const int bbase   = half * 32;
    const int fidx    = half * 128 + tile;

    // ---- one-time: weights (16/k, quad rotation q^((k>>1)&3)) + bias ----
    for (int r = 0; r < 16; r++) {
        int gate = r >> 2, hl = r & 3;
        int hp = hl >> 1;
        int q  = hp * 2 + (gate >> 1);
        int sub = ((gate & 1) << 1) | (hl & 1);
        const float* wr_h = w_hh + (size_t)(gate * HID + hu_base + hl) * HID;
        const float* wr_x = w_ih + (size_t)(gate * HID + hu_base + hl) * DIN;
        for (int k = tid; k < K; k += NTHR) {
            float v = (k < HID) ? wr_h[k] : wr_x[k - HID];
            w_sm[k * 16 + ((q ^ ((k >> 1) & 3)) << 2) + sub] = v;
        }
    }
    if (tid < 16) {
        int gate = tid >> 2, hl = tid & 3;
        int R = gate * HID + hu_base + hl;
        bias_sm[((hl >> 1) * 4 + gate) * 2 + (hl & 1)] = b_ih[R] + b_hh[R];
    }

    __shared__ unsigned s_base;
    if (tid == 0) s_base = ld_rlx(&flags[fidx]);
    __syncthreads();                          // covers weights/bias
    const unsigned base = s_base;

    u64 bias2[4];
#pragma unroll
    for (int g = 0; g < 4; g++) bias2[g] = ((const u64*)bias_sm)[rg * 4 + g];

    const int sk    = (lane >> 1) & 3;
    const int q0off = ((2 * rg)     ^ sk) << 2;
    const int q1off = ((2 * rg + 1) ^ sk) << 2;
    const int a0off = ((2 * bg)     ^ (lane & 7)) << 2;
    const int a1off = ((2 * bg + 1) ^ (lane & 7)) << 2;

    const int bb  = bg * 8 + (lane & 7);
    const int hu0 = hu_base + rg * 2;
    float c0r = c0l[(size_t)(bbase + bb) * HID + hu0];
    float c1r = c0l[(size_t)(bbase + bb) * HID + hu0 + 1];

    u64 acc[4][8];
#pragma unroll
    for (int g = 0; g < 4; g++)
#pragma unroll
        for (int b = 0; b < 8; b++) acc[g][b] = 0ull;

    // staging: warp stages batch-quad wrp; k = 32i + lane (128-k chunk)
    const int stCo = ((wrp ^ (lane & 7)) << 2);

    auto stage = [&](float* buf, const float* src, int stride, int koff) {
        const float* s0 = src + (size_t)(bbase + 4 * wrp) * stride + koff;
#pragma unroll
        for (int i = 0; i < 4; i++) {
            int k = 32 * i + lane;
            const float* s = s0 + k;
            float v0 = __ldg(s);
            float v1 = __ldg(s + stride);
            float v2 = __ldg(s + 2 * stride);
            float v3 = __ldg(s + 3 * stride);
            *(float4*)(buf + k * 32 + stCo) = make_float4(v0, v1, v2, v3);
        }
    };

    auto compute = [&](const float* buf, int kbase) {
        const float* wp = w_sm + (size_t)(kbase + lane) * 16;
        const float* ap = buf + lane * 32;
#pragma unroll
        for (int j = 0; j < 4; j++) {
            u64 w2[4];
            {
                ulonglong2 wA = *(const ulonglong2*)(wp + j * 512 + q0off);
                ulonglong2 wB = *(const ulonglong2*)(wp + j * 512 + q1off);
                w2[0] = wA.x; w2[1] = wA.y; w2[2] = wB.x; w2[3] = wB.y;
            }
            float4 aA = *(const float4*)(ap + j * 1024 + a0off);
            float4 aB = *(const float4*)(ap + j * 1024 + a1off);
            u64 a2[8];
            a2[0] = splat2(aA.x); a2[1] = splat2(aA.y);
            a2[2] = splat2(aA.z); a2[3] = splat2(aA.w);
            a2[4] = splat2(aB.x); a2[5] = splat2(aB.y);
            a2[6] = splat2(aB.z); a2[7] = splat2(aB.w);
#pragma unroll
            for (int b = 0; b < 8; b++)
#pragma unroll
                for (int g = 0; g < 4; g++)
                    acc[g][b] = ffma2(w2[g], a2[b], acc[g][b]);
        }
    };

#define ACCF(i) acc[(i) >> 3][(i) & 7]

    // ---- prologue: x-part of step 0 ----
    if constexpr (DIN == 256) {
        stage(buf1, x, DIN, 0);
        stage(buf2, x, DIN, 128);
        __syncthreads();
        compute(buf1, HID);
        compute(buf2, HID + 128);
    } else {
        stage(buf0, x, DIN, 0);
        stage(buf1, x, DIN, 128);
        __syncthreads();
        compute(buf0, HID);
        compute(buf1, HID + 128);
        __syncthreads();
        stage(buf0, x, DIN, 256);
        stage(buf1, x, DIN, 384);
        __syncthreads();
        compute(buf0, HID + 256);
        compute(buf1, HID + 384);
    }

    for (int t = 0; t < SEQ; ++t) {
        const float* __restrict__ hprev =
            t ? (h_all + (size_t)(t - 1) * BATCH * HID) : h0l;
        const bool pre = (t + 1 < SEQ);
        const float* xn = x + (size_t)(t + 1) * BATCH * DIN;

        // ---- poll h(t-1): warp 0, 128 flags of own half via v4 ----
        if (t > 0 && wrp == 0) {
            const unsigned target = base + (unsigned)t;
            const unsigned* fp = flags + half * 128 + lane * 4;
            for (;;) {
                uint4 f = ldv4_rlx(fp);
                bool ok = ((int)(f.x - target) >= 0) && ((int)(f.y - target) >= 0) &&
                          ((int)(f.z - target) >= 0) && ((int)(f.w - target) >= 0);
                if (__all_sync(0xffffffffu, ok)) break;
            }
            fence_acq();
        }
        __syncthreads();                      // S1

        if constexpr (DIN == 256) {
            stage(buf0, hprev, HID, 0);
            stage(buf1, hprev, HID, 128);
            __syncthreads();                  // S2
            compute(buf0, 0);
            compute(buf1, 128);
            stage(buf2, hprev, HID, 256);
            __syncthreads();                  // S3
            compute(buf2, 256);
            stage(buf0, hprev, HID, 384);
            if (pre) stage(buf1, xn, DIN, 0);
            __syncthreads();                  // S4
            compute(buf0, 384);
            if (pre) stage(buf2, xn, DIN, 128);
        } else {
            stage(buf0, hprev, HID, 0);
            __syncthreads();                  // S2
            compute(buf0, 0);
            stage(buf1, hprev, HID, 128);
            __syncthreads();                  // S3
            compute(buf1, 128);
            stage(buf0, hprev, HID, 256);
            __syncthreads();                  // S4
            compute(buf0, 256);
            stage(buf1, hprev, HID, 384);
            __syncthreads();                  // S5
            compute(buf1, 384);
            if (pre) stage(buf0, xn, DIN, 0);
        }

        // ---- selection-compaction reduction over 32 k-lanes ----
#pragma unroll
        for (int i = 0; i < 16; i++) {
            u64 lo = ACCF(i), hi = ACCF(i + 16);
            u64 mine = (lane & 16) ? hi : lo;
            u64 give = (lane & 16) ? lo : hi;
            ACCF(i) = fadd2(mine, shflx64(give, 16));
        }
#pragma unroll
        for (int i = 0; i < 8; i++) {
            u64 lo = ACCF(i), hi = ACCF(i + 8);
            u64 mine = (lane & 8) ? hi : lo;
            u64 give = (lane & 8) ? lo : hi;
            ACCF(i) = fadd2(mine, shflx64(give, 8));
        }
#pragma unroll
        for (int i = 0; i < 4; i++) {
            u64 lo = ACCF(i), hi = ACCF(i + 4);
            u64 mine = (lane & 4) ? hi : lo;
            u64 give = (lane & 4) ? lo : hi;
            ACCF(i) = fadd2(mine, shflx64(give, 4));
        }
#pragma unroll
        for (int i = 0; i < 2; i++) {
            u64 lo = ACCF(i), hi = ACCF(i + 2);
            u64 mine = (lane & 2) ? hi : lo;
            u64 give = (lane & 2) ? lo : hi;
            ACCF(i) = fadd2(mine, shflx64(give, 2));
        }
        {
            u64 lo = ACCF(0), hi = ACCF(1);
            u64 mine = (lane & 1) ? hi : lo;
            u64 give = (lane & 1) ? lo : hi;
            ACCF(0) = fadd2(mine, shflx64(give, 1));
        }
        u64 fin = ACCF(0);

        u64 gv[4];
#pragma unroll
        for (int g = 0; g < 4; g++)
            gv[g] = fadd2(shfli64(fin, g * 8 + (lane & 7)), bias2[g]);

        float ig0 = sigf(f2lo(gv[0])), ig1 = sigf(f2hi(gv[0]));
        float fg0 = sigf(f2lo(gv[1])), fg1 = sigf(f2hi(gv[1]));
        float gg0 = tanhfast(f2lo(gv[2])), gg1 = tanhfast(f2hi(gv[2]));
        float og0 = sigf(f2lo(gv[3])), og1 = sigf(f2hi(gv[3]));
        c0r = fg0 * c0r + ig0 * gg0;
        c1r = fg1 * c1r + ig1 * gg1;
        float h0v = og0 * tanhfast(c0r);
        float h1v = og1 * tanhfast(c1r);

        if (lane < 8)
            *(float2*)&h_all[((size_t)t * BATCH + bbase + bb) * HID + hu0] =
                make_float2(h0v, h1v);

        // zero acc for next step's x accumulation
#pragma unroll
        for (int g = 0; g < 4; g++)
#pragma unroll
            for (int b = 0; b < 8; b++) acc[g][b] = 0ull;

        if (pre) {
            __threadfence();
            __syncthreads();                  // S5 (L0) / S6 (L1)
            if (tid == 0) st_rlx(&flags[fidx], base + (unsigned)(t + 1));
            if constexpr (DIN == 256) {
                compute(buf1, HID);           // x chunks of t+1
                compute(buf2, HID + 128);
            } else {
                compute(buf0, HID);
                stage(buf1, xn, DIN, 128);
                __syncthreads();              // S7
                compute(buf1, HID + 128);
                stage(buf0, xn, DIN, 256);
                __syncthreads();              // S8
                compute(buf0, HID + 256);
                stage(buf1, xn, DIN, 384);
                __syncthreads();              // S9
                compute(buf1, HID + 384);
            }
        }
    }
#undef ACCF
}

// ---------------- output head: sigmoid(h1 . w_out + b_out) ----------------
__global__ void __launch_bounds__(256)
head_kernel(const float* __restrict__ h_all, const float* __restrict__ w_out,
            const float* __restrict__ b_out, float* __restrict__ out)
{
    __shared__ float wsm[HID];
    int t = blockIdx.x;
    for (int i = threadIdx.x; i < HID; i += 256) wsm[i] = w_out[i];
    __syncthreads();
    int wrp = threadIdx.x >> 5, lane = threadIdx.x & 31;
    float bo = b_out[0];
#pragma unroll
    for (int rb = 0; rb < 8; ++rb) {
        int b = wrp * 8 + rb;
        const float* h = h_all + ((size_t)t * BATCH + b) * HID;
        float s = 0.f;
#pragma unroll
        for (int j = 0; j < 16; ++j) s += h[lane + 32 * j] * wsm[lane + 32 * j];
#pragma unroll
        for (int m = 16; m > 0; m >>= 1) s += __shfl_xor_sync(0xffffffffu, s, m);
        if (lane == 0) out[(size_t)t * BATCH + b] = 1.f / (1.f + expf(-(s + bo)));
    }
}

extern "C" void kernel_launch(void* const* d_in, const int* in_sizes, int n_in,
                              void* d_out, int out_size)
{
    (void)in_sizes; (void)n_in; (void)out_size;
    const float* input = (const float*)d_in[0];
    const float* h0    = (const float*)d_in[1];
    const float* c0    = (const float*)d_in[2];
    const float* w_ih0 = (const float*)d_in[3];
    const float* w_hh0 = (const float*)d_in[4];
    const float* b_ih0 = (const float*)d_in[5];
    const float* b_hh0 = (const float*)d_in[6];
    const float* w_ih1 = (const float*)d_in[7];
    const float* w_hh1 = (const float*)d_in[8];
    const float* b_ih1 = (const float*)d_in[9];
    const float* b_hh1 = (const float*)d_in[10];
    const float* w_out = (const float*)d_in[11];
    const float* b_out = (const float*)d_in[12];
    float* out = (float*)d_out;

    float *h0p, *h1p;
    unsigned *fA, *fB;
    cudaGetSymbolAddress((void**)&h0p, g_h0_all);
    cudaGetSymbolAddress((void**)&h1p, g_h1_all);
    cudaGetSymbolAddress((void**)&fA,  g_flagsA);
    cudaGetSymbolAddress((void**)&fB,  g_flagsB);

    const int smem0 = (768  * 16 + 3 * 128 * 32 + 16) * (int)sizeof(float); // 98,368
    const int smem1 = (1024 * 16 + 2 * 128 * 32 + 16) * (int)sizeof(float); // 98,368
    cudaFuncSetAttribute(lstm_layer<256>, cudaFuncAttributeMaxDynamicSharedMemorySize, smem0);
    cudaFuncSetAttribute(lstm_layer<512>, cudaFuncAttributeMaxDynamicSharedMemorySize, smem1);

    lstm_layer<256><<<256, NTHR, smem0>>>(input, h0, c0,
                                          w_ih0, w_hh0, b_ih0, b_hh0, h0p, fA);
    lstm_layer<512><<<256, NTHR, smem1>>>(h0p, h0 + BATCH * HID, c0 + BATCH * HID,
                                          w_ih1, w_hh1, b_ih1, b_hh1, h1p, fB);
    head_kernel<<<SEQ, 256>>>(h1p, w_out, b_out, out);
}